// round 4
// baseline (speedup 1.0000x reference)
#include <cuda_runtime.h>
#include <cuda_bf16.h>
#include <math.h>

#define Bsz 512
#define Ssz 512
#define Tsz 128
#define NEGV -10000.0f
#define NCTA 256     // 2 batches per CTA

// scratch (no allocations allowed)
__device__ float g_fwd[Bsz];
__device__ float g_gold[Bsz];
__device__ int   g_len[Bsz];
__device__ int   g_order[Bsz];
__device__ int   g_slen[Bsz];

// ---- packed f32x2 helpers (sm_100+) ----
__device__ __forceinline__ unsigned long long pack2(float lo, float hi) {
    unsigned long long r;
    asm("mov.b64 %0, {%1, %2};" : "=l"(r) : "f"(lo), "f"(hi));
    return r;
}
__device__ __forceinline__ void ffma2(unsigned long long& d,
                                      unsigned long long a,
                                      unsigned long long b) {
    asm("fma.rn.f32x2 %0, %1, %2, %0;" : "+l"(d) : "l"(a), "l"(b));
}
__device__ __forceinline__ unsigned long long addp(unsigned long long a,
                                                   unsigned long long b) {
    unsigned long long r;
    asm("add.rn.f32x2 %0, %1, %2;" : "=l"(r) : "l"(a), "l"(b));
    return r;
}
__device__ __forceinline__ float unpack_sum(unsigned long long a) {
    float lo, hi;
    asm("mov.b64 {%0, %1}, %2;" : "=f"(lo), "=f"(hi) : "l"(a));
    return lo + hi;
}

// ---------------------------------------------------------------------------
// Kernel 1: lengths
// ---------------------------------------------------------------------------
__global__ __launch_bounds__(128)
void crf_len_kernel(const float* __restrict__ mask)
{
    __shared__ float sh[4];
    const int b = blockIdx.x, tid = threadIdx.x;
    const int warp = tid >> 5, lane = tid & 31;
    const float4* mb = reinterpret_cast<const float4*>(mask + (size_t)b * Ssz);
    float4 v = mb[tid];
    float s = v.x + v.y + v.z + v.w;
    #pragma unroll
    for (int off = 16; off > 0; off >>= 1)
        s += __shfl_xor_sync(0xffffffffu, s, off);
    if (lane == 0) sh[warp] = s;
    __syncthreads();
    if (tid == 0)
        g_len[b] = (int)(sh[0] + sh[1] + sh[2] + sh[3] + 0.5f);
}

// ---------------------------------------------------------------------------
// Kernel 2: bitonic sort 512 keys, descending by len
// ---------------------------------------------------------------------------
__global__ __launch_bounds__(512)
void crf_sort_kernel()
{
    __shared__ int keys[Bsz];
    const int tid = threadIdx.x;
    keys[tid] = (g_len[tid] << 16) | tid;
    __syncthreads();
    for (int k = 2; k <= Bsz; k <<= 1) {
        for (int j = k >> 1; j > 0; j >>= 1) {
            int ixj = tid ^ j;
            if (ixj > tid) {
                int a = keys[tid];
                int b2 = keys[ixj];
                bool up = ((tid & k) == 0);
                if (up ? (a < b2) : (a > b2)) {
                    keys[tid] = b2;
                    keys[ixj] = a;
                }
            }
            __syncthreads();
        }
    }
    g_order[tid] = keys[tid] & 0xFFFF;
    g_slen[tid]  = keys[tid] >> 16;
}

// ---------------------------------------------------------------------------
// Kernel 3: forward + gold. One CTA = TWO batches (rank c and rank 511-c).
// Thread i owns E-row i (shared by both batches), alphaA/alphaB in registers.
// One barrier per timestep covers both batches; matvecs interleaved for ILP.
// Stale-shift trick: c_known is alpha_0 of the previous step.
// ---------------------------------------------------------------------------
__global__ __launch_bounds__(128, 2)
void crf_forward_kernel(const float* __restrict__ x,
                        const int*   __restrict__ tags,
                        const float* __restrict__ trans)
{
    __shared__ __align__(16) float sh_pA[2][Tsz];
    __shared__ __align__(16) float sh_pB[2][Tsz];
    __shared__ float sh_cA[2], sh_cB[2];
    __shared__ float sh_red[4];

    const int tid  = threadIdx.x;
    const int lane = tid & 31;
    const int warp = tid >> 5;
    const int c    = blockIdx.x;
    const int bA   = g_order[c];           // long batch
    const int bB   = g_order[511 - c];     // short batch
    const int lenA = g_slen[c];
    const int lenB = g_slen[511 - c];      // lenB <= lenA

    // E row tid: e2[2q],e2[2q+1] cover trans[tid][4q..4q+3]
    unsigned long long e2[64];
    const float4* trow = reinterpret_cast<const float4*>(trans + tid * Tsz);
    #pragma unroll
    for (int q = 0; q < 32; q++) {
        float4 v4 = trow[q];
        e2[2*q    ] = pack2(__expf(v4.x), __expf(v4.y));
        e2[2*q + 1] = pack2(__expf(v4.z), __expf(v4.w));
    }

    float alphaA = (tid == 0) ? 0.0f : NEGV;
    float alphaB = alphaA;
    float cA = 0.0f, cB = 0.0f;

    const float* xbA = x + (size_t)bA * Ssz * Tsz;
    const float* xbB = x + (size_t)bB * Ssz * Tsz;
    float xrA = __ldg(xbA + tid);
    float xrB = __ldg(xbB + tid);

    for (int t = 0; t < lenA; t++) {
        const int buf = t & 1;
        const bool act = (t < lenB);

        sh_pA[buf][tid] = __expf(alphaA - cA);
        if (tid == 0) sh_cA[buf] = alphaA;
        if (act) {
            sh_pB[buf][tid] = __expf(alphaB - cB);
            if (tid == 0) sh_cB[buf] = alphaB;
        }
        int tnA = (t + 1 < lenA) ? (t + 1) : t;
        float xnA = __ldg(xbA + (size_t)tnA * Tsz + tid);
        float xnB = (t + 1 < lenB) ? __ldg(xbB + (size_t)(t + 1) * Tsz + tid) : 0.0f;
        __syncthreads();                       // one barrier, both batches

        float cAn = sh_cA[buf];
        const ulonglong2* pA2 = reinterpret_cast<const ulonglong2*>(sh_pA[buf]);

        if (act) {
            float cBn = sh_cB[buf];
            const ulonglong2* pB2 = reinterpret_cast<const ulonglong2*>(sh_pB[buf]);
            unsigned long long A0=0ull,A1=0ull,A2=0ull,A3=0ull;
            unsigned long long B0=0ull,B1=0ull,B2=0ull,B3=0ull;
            #pragma unroll
            for (int q = 0; q < 32; q += 2) {
                ulonglong2 ua0 = pA2[q+0];
                ulonglong2 ua1 = pA2[q+1];
                ulonglong2 ub0 = pB2[q+0];
                ulonglong2 ub1 = pB2[q+1];
                ffma2(A0, e2[2*q + 0], ua0.x);
                ffma2(B0, e2[2*q + 0], ub0.x);
                ffma2(A1, e2[2*q + 1], ua0.y);
                ffma2(B1, e2[2*q + 1], ub0.y);
                ffma2(A2, e2[2*q + 2], ua1.x);
                ffma2(B2, e2[2*q + 2], ub1.x);
                ffma2(A3, e2[2*q + 3], ua1.y);
                ffma2(B3, e2[2*q + 3], ub1.y);
            }
            float sA = unpack_sum(addp(addp(A0, A1), addp(A2, A3)));
            float sB = unpack_sum(addp(addp(B0, B1), addp(B2, B3)));
            alphaA = cA + __logf(sA) + xrA;
            alphaB = cB + __logf(sB) + xrB;
            cB = cBn;
            xrB = xnB;
        } else {
            unsigned long long A0=0ull,A1=0ull,A2=0ull,A3=0ull,
                               A4=0ull,A5=0ull,A6=0ull,A7=0ull;
            #pragma unroll
            for (int q = 0; q < 32; q += 4) {
                ulonglong2 u0 = pA2[q+0];
                ulonglong2 u1 = pA2[q+1];
                ulonglong2 u2 = pA2[q+2];
                ulonglong2 u3 = pA2[q+3];
                ffma2(A0, e2[2*q + 0], u0.x);
                ffma2(A1, e2[2*q + 1], u0.y);
                ffma2(A2, e2[2*q + 2], u1.x);
                ffma2(A3, e2[2*q + 3], u1.y);
                ffma2(A4, e2[2*q + 4], u2.x);
                ffma2(A5, e2[2*q + 5], u2.y);
                ffma2(A6, e2[2*q + 6], u3.x);
                ffma2(A7, e2[2*q + 7], u3.y);
            }
            unsigned long long s01 = addp(addp(A0, A1), addp(A2, A3));
            unsigned long long s23 = addp(addp(A4, A5), addp(A6, A7));
            float sA = unpack_sum(addp(s01, s23));
            alphaA = cA + __logf(sA) + xrA;
        }
        cA  = cAn;
        xrA = xnA;
    }

    // ---- finalize both batches: fwd = LSE_i(alpha_i + trans[END=1][i]) ----
    float tEnd = __ldg(trans + 1 * Tsz + tid);
    #pragma unroll
    for (int g = 0; g < 2; g++) {
        float v = ((g == 0) ? alphaA : alphaB) + tEnd;
        float wm = v;
        #pragma unroll
        for (int off = 16; off > 0; off >>= 1)
            wm = fmaxf(wm, __shfl_xor_sync(0xffffffffu, wm, off));
        if (lane == 0) sh_red[warp] = wm;
        __syncthreads();
        float m = fmaxf(fmaxf(sh_red[0], sh_red[1]), fmaxf(sh_red[2], sh_red[3]));
        float ws = __expf(v - m);
        #pragma unroll
        for (int off = 16; off > 0; off >>= 1)
            ws += __shfl_xor_sync(0xffffffffu, ws, off);
        __syncthreads();
        if (lane == 0) sh_red[warp] = ws;
        __syncthreads();
        if (tid == 0)
            g_fwd[(g == 0) ? bA : bB] =
                m + __logf(sh_red[0] + sh_red[1] + sh_red[2] + sh_red[3]);
        __syncthreads();
    }

    // ---- gold scores for both batches ----
    #pragma unroll
    for (int g = 0; g < 2; g++) {
        const int    b   = (g == 0) ? bA : bB;
        const int    len = (g == 0) ? lenA : lenB;
        const float* xb  = (g == 0) ? xbA : xbB;
        const int*   tg  = tags + (size_t)b * Ssz;
        float acc = 0.0f;
        for (int t2 = tid; t2 < len; t2 += 128) {
            int tnext = tg[t2 + 1];
            int tcur  = tg[t2];
            acc += xb[(size_t)t2 * Tsz + tnext] + __ldg(trans + tnext * Tsz + tcur);
        }
        #pragma unroll
        for (int off = 16; off > 0; off >>= 1)
            acc += __shfl_xor_sync(0xffffffffu, acc, off);
        if (lane == 0) sh_red[warp] = acc;
        __syncthreads();
        if (tid == 0) {
            float total = sh_red[0] + sh_red[1] + sh_red[2] + sh_red[3];
            g_gold[b] = total + __ldg(trans + 1 * Tsz + tg[len]);
        }
        __syncthreads();
    }
}

// ---------------------------------------------------------------------------
// Kernel 4: out[0] = mean(fwd - gold)
// ---------------------------------------------------------------------------
__global__ __launch_bounds__(512)
void crf_reduce_kernel(float* __restrict__ out)
{
    __shared__ float sh[16];
    const int tid  = threadIdx.x;
    const int warp = tid >> 5;
    const int lane = tid & 31;

    float d = g_fwd[tid] - g_gold[tid];
    #pragma unroll
    for (int off = 16; off > 0; off >>= 1)
        d += __shfl_xor_sync(0xffffffffu, d, off);
    if (lane == 0) sh[warp] = d;
    __syncthreads();
    if (warp == 0) {
        float v = (lane < 16) ? sh[lane] : 0.0f;
        #pragma unroll
        for (int off = 8; off > 0; off >>= 1)
            v += __shfl_xor_sync(0xffffffffu, v, off);
        if (lane == 0) out[0] = v * (1.0f / (float)Bsz);
    }
}

extern "C" void kernel_launch(void* const* d_in, const int* in_sizes, int n_in,
                              void* d_out, int out_size)
{
    const float* x     = (const float*)d_in[0];
    const int*   tags  = (const int*)  d_in[1];
    const float* mask  = (const float*)d_in[2];
    const float* trans = (const float*)d_in[3];
    float* out = (float*)d_out;

    crf_len_kernel    <<<Bsz,  128>>>(mask);
    crf_sort_kernel   <<<1,    512>>>();
    crf_forward_kernel<<<NCTA, 128>>>(x, tags, trans);
    crf_reduce_kernel <<<1,    512>>>(out);
}